// round 8
// baseline (speedup 1.0000x reference)
#include <cuda_runtime.h>
#include <cuda_bf16.h>
#include <math.h>

// B=16, T=32 (early exit: only token 31 used; all ops causal), DM=256,
// DI=512, DS=16, DR=16, DCONV=4, L=4. One persistent megakernel, grid-wide
// stages; 128x128 f32x2 GEMM tiles with split-K; fast load-poll barrier.

#define NB      16
#define TT      32
#define NTOK    (NB*TT)      // 512
#define DM      256
#define DI      512
#define DS      16
#define DR      16
#define NL      4
#define THREADS 256
#define SPLIT_IN  4
#define SPLIT_OUT 16

// scratch (device globals; no allocation allowed)
__device__ __align__(16) float g_feat[NTOK*DM];
__device__ __align__(16) float g_xzp [SPLIT_IN][NTOK*2*DI];
__device__ __align__(16) float g_dbl [NTOK*48];
__device__ __align__(16) float g_xct [NB*DI*TT];
__device__ __align__(16) float g_ztr [NB*DI*TT];
__device__ __align__(16) float g_dtt [NB*DI*TT];
__device__ __align__(16) float g_y   [NTOK*DI];
__device__ __align__(16) float g_outp[SPLIT_OUT][NTOK*DM];

__device__ unsigned          g_cnt;
__device__ volatile unsigned g_rel;

__global__ void reset_bar() { g_cnt = 0u; g_rel = 0u; }

// fast grid barrier: one atomic arrival per block; waiters poll with LDG
__device__ __forceinline__ void gsync(unsigned& gen) {
    __syncthreads();
    if (threadIdx.x == 0) {
        gen += 1u;
        __threadfence();
        unsigned a = atomicAdd(&g_cnt, 1u) + 1u;
        if (a == gen * gridDim.x) {
            __threadfence();
            g_rel = gen;
        } else {
            while (g_rel < gen) { }
        }
        __threadfence();
    }
    __syncthreads();
}

// ---- packed dual-fp32 (Blackwell FFMA2, PTX-only) -------------------------
typedef unsigned long long ull;
__device__ __forceinline__ ull pk2(float lo, float hi) {
    ull r; asm("mov.b64 %0, {%1, %2};" : "=l"(r) : "f"(lo), "f"(hi)); return r;
}
__device__ __forceinline__ void fma2(ull& d, ull a, ull b) {
    asm("fma.rn.f32x2 %0, %1, %2, %0;" : "+l"(d) : "l"(a), "l"(b));
}
__device__ __forceinline__ float2 upk2(ull v) {
    float2 f; asm("mov.b64 {%0, %1}, %2;" : "=f"(f.x), "=f"(f.y) : "l"(v)); return f;
}

#define SMTOT 4224   // gemm: 2 * 16*132 ; scan needs 3600

// ---------------------------------------------------------------------------
// 128x128 tile SGEMM: C[bm:+128, bn:+128] = A[.,kbeg:kend] @ B^T
// 256 thr, 8x8 microtile (rows ty*4,64+ty*4; cols tx*4,64+tx*4), f32x2 acc.
// ---------------------------------------------------------------------------
__device__ __forceinline__ void gemm_tile128(const float* __restrict__ A,
                                             const float* __restrict__ B,
                                             float* __restrict__ C,
                                             int N, int K, int bm, int bn,
                                             int kbeg, int kend, float* sm)
{
    float (*As)[132] = (float(*)[132])sm;
    float (*Bs)[132] = (float(*)[132])(sm + 16*132);
    const int tid = threadIdx.x;
    const int ty = tid >> 4, tx = tid & 15;
    const int r0 = ty*4, r1 = 64 + ty*4;
    const int c0 = tx*4, c1 = 64 + tx*4;
    ull acc[8][4];
    #pragma unroll
    for (int r = 0; r < 8; r++)
        #pragma unroll
        for (int c = 0; c < 4; c++) acc[r][c] = 0ull;

    for (int k0 = kbeg; k0 < kend; k0 += 16) {
        #pragma unroll
        for (int j = 0; j < 2; j++) {
            int i = tid + j*256;             // 512 float4 items
            int row = i >> 2, kq = (i & 3)*4;
            float4 av = __ldcg((const float4*)(A + (size_t)(bm+row)*K + k0 + kq));
            As[kq+0][row]=av.x; As[kq+1][row]=av.y; As[kq+2][row]=av.z; As[kq+3][row]=av.w;
            float4 bv = *(const float4*)(B + (size_t)(bn+row)*K + k0 + kq);
            Bs[kq+0][row]=bv.x; Bs[kq+1][row]=bv.y; Bs[kq+2][row]=bv.z; Bs[kq+3][row]=bv.w;
        }
        __syncthreads();
        #pragma unroll
        for (int k = 0; k < 16; k++) {
            float4 aA = *(const float4*)&As[k][r0];
            float4 aB = *(const float4*)&As[k][r1];
            float4 bA = *(const float4*)&Bs[k][c0];
            float4 bB = *(const float4*)&Bs[k][c1];
            ull bp[4] = { pk2(bA.x,bA.y), pk2(bA.z,bA.w),
                          pk2(bB.x,bB.y), pk2(bB.z,bB.w) };
            float ar[8] = {aA.x,aA.y,aA.z,aA.w,aB.x,aB.y,aB.z,aB.w};
            #pragma unroll
            for (int r = 0; r < 8; r++) {
                ull a2 = pk2(ar[r], ar[r]);
                #pragma unroll
                for (int c = 0; c < 4; c++) fma2(acc[r][c], a2, bp[c]);
            }
        }
        __syncthreads();
    }
    #pragma unroll
    for (int r = 0; r < 8; r++) {
        int row = bm + ((r < 4) ? (r0 + r) : (r1 + r - 4));
        float2 p0 = upk2(acc[r][0]), p1 = upk2(acc[r][1]);
        float2 p2 = upk2(acc[r][2]), p3 = upk2(acc[r][3]);
        *(float4*)(C + (size_t)row*N + bn + c0) = make_float4(p0.x,p0.y,p1.x,p1.y);
        *(float4*)(C + (size_t)row*N + bn + c1) = make_float4(p2.x,p2.y,p3.x,p3.y);
    }
}

__device__ __forceinline__ void stage_gemm(const float* A, const float* W,
                                           float* Cp, int M, int N, int K,
                                           int S, float* sm)
{
    int ntn = N/128, nt = (M/128)*ntn;
    int ks = K / S;
    for (int w = blockIdx.x; w < nt*S; w += gridDim.x) {
        int s = w / nt, t = w - s*nt;
        int bm = (t / ntn)*128, bn = (t - (t/ntn)*ntn)*128;
        gemm_tile128(A, W, Cp + (size_t)s*M*N, N, K, bm, bn, s*ks, s*ks+ks, sm);
    }
}

// ---------------------------------------------------------------------------
__global__ void __launch_bounds__(THREADS, 2)
mega(const float* __restrict__ x,
     const float* __restrict__ ep,  const float* __restrict__ ef,
     const float* __restrict__ ed,
     const float* __restrict__ plw, const float* __restrict__ plb,
     const float* __restrict__ piw, const float* __restrict__ pib,
     const float* __restrict__ fw,  const float* __restrict__ fb,
     const float* __restrict__ tg,  const float* __restrict__ tb,
     const float* __restrict__ ng,  const float* __restrict__ nb,
     const float* __restrict__ ipw, const float* __restrict__ cw,
     const float* __restrict__ cb,  const float* __restrict__ xpw,
     const float* __restrict__ dtw, const float* __restrict__ dtb,
     const float* __restrict__ alog,const float* __restrict__ dp,
     const float* __restrict__ opw,
     const float* __restrict__ w1,  const float* __restrict__ b1,
     const float* __restrict__ w2,  const float* __restrict__ b2,
     float* __restrict__ out)
{
    __shared__ __align__(16) float SMF[SMTOT];
    unsigned gen = 0u;
    const int tid = threadIdx.x;
    const int G = gridDim.x;

    // ---------------- featurize + tok LN -> g_feat -----------------------
    {
        float* cat = SMF;          // 136
        float* red = SMF + 144;    // 256
        for (int tok = blockIdx.x; tok < NTOK; tok += G) {
            int b = tok >> 5, tl = tok & 31;
            const float* xr = x + (b*1024 + tl)*5;
            int d = tid;
            if (d < 136) {
                float v;
                if (d < 32)       { int p=(int)xr[0]; p=min(max(p,0),255); v=ep[p*32+d]; }
                else if (d < 64)  { v = xr[1]*plw[d-32] + plb[d-32]; }
                else if (d < 96)  { int f=(int)xr[2]; f=min(max(f,0),63); v=ef[f*32+(d-64)]; }
                else if (d < 128) { v = xr[3]*piw[d-96] + pib[d-96]; }
                else              { int dd=(int)xr[4]; dd=min(max(dd,0),1); v=ed[dd*8+(d-128)]; }
                cat[d] = v;
            }
            __syncthreads();
            float acc = fb[d];
            const float* wrow = fw + d*136;
            #pragma unroll 8
            for (int j = 0; j < 136; j++) acc += cat[j]*wrow[j];
            red[d] = acc; __syncthreads();
            for (int off=128; off; off>>=1){ if (d<off) red[d]+=red[d+off]; __syncthreads(); }
            float mean = red[0]*(1.f/DM); __syncthreads();
            float dv = acc-mean; red[d]=dv*dv; __syncthreads();
            for (int off=128; off; off>>=1){ if (d<off) red[d]+=red[d+off]; __syncthreads(); }
            float var = red[0]*(1.f/DM);
            g_feat[tok*DM + d] = dv*rsqrtf(var+1e-5f)*tg[d] + tb[d];
            __syncthreads();
        }
    }
    gsync(gen);

    for (int l = 0; l < NL; l++) {
        const float* ipw_l = ipw + (size_t)l*2*DI*DM;
        const float* cw_l  = cw  + (size_t)l*DI*4;
        const float* cb_l  = cb  + (size_t)l*DI;
        const float* xpw_l = xpw + (size_t)l*48*DI;
        const float* dtw_l = dtw + (size_t)l*DI*DR;
        const float* dtb_l = dtb + (size_t)l*DI;
        const float* al_l  = alog+ (size_t)l*DI*DS;
        const float* dp_l  = dp  + (size_t)l*DI;
        const float* opw_l = opw + (size_t)l*DM*DI;

        // -------- in_proj: xz = feat @ ipw^T (split-K=4 partials) --------
        stage_gemm(g_feat, ipw_l, &g_xzp[0][0], NTOK, 2*DI, DM, SPLIT_IN, SMF);
        gsync(gen);

        // -------- conv+SiLU, x_proj, dt (per token) ----------------------
        {
            float* xcs  = SMF;        // 512
            float* dbls = SMF + 512;  // 48
            for (int tok = blockIdx.x; tok < NTOK; tok += G) {
                int b = tok >> 5, tl = tok & 31;
                #pragma unroll
                for (int r = 0; r < 2; r++) {
                    int d = tid + r*256;
                    float acc = cb_l[d];
                    #pragma unroll
                    for (int k = 0; k < 4; k++) {
                        int tt = tl - 3 + k;
                        if (tt >= 0) {
                            int off = (tok-3+k)*(2*DI) + d;
                            float s = 0.f;
                            #pragma unroll
                            for (int sp = 0; sp < SPLIT_IN; sp++)
                                s += __ldcg(&g_xzp[sp][off]);
                            acc += cw_l[d*4+k] * s;
                        }
                    }
                    xcs[d] = acc / (1.f + __expf(-acc));
                }
                __syncthreads();
                int warp = tid >> 5, lane = tid & 31;
                #pragma unroll
                for (int i = 0; i < 6; i++) {
                    int o = warp*6 + i;
                    const float* wr = xpw_l + o*DI;
                    float p = 0.f;
                    #pragma unroll
                    for (int j = 0; j < 16; j++) p += xcs[j*32+lane]*wr[j*32+lane];
                    #pragma unroll
                    for (int off = 16; off; off >>= 1)
                        p += __shfl_down_sync(0xffffffffu, p, off);
                    if (lane == 0) { dbls[o] = p; g_dbl[tok*48 + o] = p; }
                }
                __syncthreads();
                #pragma unroll
                for (int r = 0; r < 2; r++) {
                    int d = tid + r*256;
                    float v = dtb_l[d];
                    const float* dwr = dtw_l + d*DR;
                    #pragma unroll
                    for (int rr = 0; rr < DR; rr++) v += dbls[rr]*dwr[rr];
                    int tri = (b*DI + d)*TT + tl;
                    g_dtt[tri] = (v > 20.f) ? v : log1pf(__expf(v));
                    g_xct[tri] = xcs[d];
                    int zo = tok*2*DI + DI + d;
                    float zv = 0.f;
                    #pragma unroll
                    for (int sp = 0; sp < SPLIT_IN; sp++)
                        zv += __ldcg(&g_xzp[sp][zo]);
                    g_ztr[tri] = zv;
                }
                __syncthreads();
            }
        }
        gsync(gen);

        // -------- selective scan: serial t, parallel (d,n) ---------------
        {
            float* Bsm = SMF;            // 512
            float* Csm = SMF + 512;      // 512
            float* ws  = SMF + 1024;     // 512
            float* es  = SMF + 1536;     // 512
            float* xs  = SMF + 2048;     // 512
            float* zs  = SMF + 2560;     // 512
            float* dts = SMF + 3072;     // 512
            float* A0s = SMF + 3584;     // 16
            for (int chunk = blockIdx.x; chunk < NB*32; chunk += G) {
                int b = chunk >> 5;
                int d0 = (chunk & 31) * 16;
                if (tid < 16) A0s[tid] = -__expf(al_l[(d0+tid)*DS]);
                __syncthreads();
                #pragma unroll
                for (int i = tid; i < 512; i += 256) {
                    int t = i >> 4, n = i & 15;
                    const float* row = g_dbl + (b*TT + t)*48;
                    Bsm[t*16+n] = __ldcg(&row[16+n]);
                    Csm[t*16+n] = __ldcg(&row[32+n]);
                    int ch = i >> 5, tt = i & 31;
                    int tri = (b*DI + d0 + ch)*TT + tt;
                    float dtv = __ldcg(&g_dtt[tri]);
                    float xv  = __ldcg(&g_xct[tri]);
                    dts[ch*32+tt] = dtv;
                    ws [ch*32+tt] = dtv*xv;
                    xs [ch*32+tt] = xv;
                    zs [ch*32+tt] = __ldcg(&g_ztr[tri]);
                    es [ch*32+tt] = __expf(dtv * A0s[ch]);
                }
                __syncthreads();
                int lane = tid & 31;
                int ch = (tid >> 5)*2 + (lane >> 4);
                int n = lane & 15;
                int d = d0 + ch;
                float An = -__expf(al_l[d*DS + n]);
                float A0 = A0s[ch];
                bool fast = fabsf(An - (float)(n+1)*A0) <= 1e-5f*fabsf(An) + 1e-7f;
                fast = __all_sync(0xffffffffu, fast);
                float Dd = dp_l[d];
                float h = 0.f;
                int np = n + 1;
                if (fast) {
                    #pragma unroll 4
                    for (int t = 0; t < TT; t++) {
                        float e1 = es[ch*32+t];
                        float p2 = e1*e1, p4 = p2*p2, p8 = p4*p4;
                        float a = 1.f;
                        if (np & 1)  a *= e1;
                        if (np & 2)  a *= p2;
                        if (np & 4)  a *= p4;
                        if (np & 8)  a *= p8;
                        if (np & 16) a *= p8*p8;
                        h = a*h + ws[ch*32+t]*Bsm[t*16+n];
                        float v = h*Csm[t*16+n];
                        v += __shfl_xor_sync(0xffffffffu, v, 8);
                        v += __shfl_xor_sync(0xffffffffu, v, 4);
                        v += __shfl_xor_sync(0xffffffffu, v, 2);
                        v += __shfl_xor_sync(0xffffffffu, v, 1);
                        if (n == 0) {
                            float zv = zs[ch*32+t];
                            float sz = zv / (1.f + __expf(-zv));
                            g_y[(b*TT+t)*DI + d] = (v + Dd*xs[ch*32+t]) * sz;
                        }
                    }
                } else {
                    #pragma unroll 4
                    for (int t = 0; t < TT; t++) {
                        float a = __expf(dts[ch*32+t]*An);
                        h = a*h + ws[ch*32+t]*Bsm[t*16+n];
                        float v = h*Csm[t*16+n];
                        v += __shfl_xor_sync(0xffffffffu, v, 8);
                        v += __shfl_xor_sync(0xffffffffu, v, 4);
                        v += __shfl_xor_sync(0xffffffffu, v, 2);
                        v += __shfl_xor_sync(0xffffffffu, v, 1);
                        if (n == 0) {
                            float zv = zs[ch*32+t];
                            float sz = zv / (1.f + __expf(-zv));
                            g_y[(b*TT+t)*DI + d] = (v + Dd*xs[ch*32+t]) * sz;
                        }
                    }
                }
                __syncthreads();
            }
        }
        gsync(gen);

        // -------- out_proj: split-K=16 partials --------------------------
        stage_gemm(g_y, opw_l, &g_outp[0][0], NTOK, DM, DI, SPLIT_OUT, SMF);
        gsync(gen);

        // -------- residual + LN -> feat ----------------------------------
        {
            float* red = SMF;
            for (int tok = blockIdx.x; tok < NTOK; tok += G) {
                int d = tid;
                int o = tok*DM + d;
                float v = __ldcg(&g_feat[o]);
                #pragma unroll
                for (int sp = 0; sp < SPLIT_OUT; sp++)
                    v += __ldcg(&g_outp[sp][o]);
                red[d] = v; __syncthreads();
                for (int off=128; off; off>>=1){ if (d<off) red[d]+=red[d+off]; __syncthreads(); }
                float mean = red[0]*(1.f/DM); __syncthreads();
                float dv = v-mean; red[d]=dv*dv; __syncthreads();
                for (int off=128; off; off>>=1){ if (d<off) red[d]+=red[d+off]; __syncthreads(); }
                float var = red[0]*(1.f/DM);
                g_feat[o] = dv*rsqrtf(var+1e-5f)*ng[d] + nb[d];
                __syncthreads();
            }
        }
        gsync(gen);
    }

    // ---------------- classifier on token 31 ------------------------------
    if (blockIdx.x < NB) {
        float* hs = SMF;
        int b = blockIdx.x, j = tid;
        const float* fr = g_feat + (b*TT + 31)*DM;
        if (j < 128) {
            float acc = b1[j];
            const float* wr = w1 + j*DM;
            #pragma unroll 8
            for (int d = 0; d < DM; d++) acc += __ldcg(&fr[d])*wr[d];
            hs[j] = fmaxf(acc, 0.f);
        }
        __syncthreads();
        if (j < 2) {
            float o = b2[j];
            const float* w2r = w2 + j*128;
            #pragma unroll 8
            for (int k = 0; k < 128; k++) o += hs[k]*w2r[k];
            out[b*2 + j] = o;
        }
    }
}

// ---------------------------------------------------------------------------
extern "C" void kernel_launch(void* const* d_in, const int* in_sizes, int n_in,
                              void* d_out, int out_size)
{
    static int G = 0;
    if (!G) {
        int dev = 0; cudaGetDevice(&dev);
        int nsm = 0; cudaDeviceGetAttribute(&nsm, cudaDevAttrMultiProcessorCount, dev);
        int bpm = 0;
        cudaOccupancyMaxActiveBlocksPerMultiprocessor(&bpm, mega, THREADS, 0);
        if (bpm < 1) bpm = 1;
        if (bpm > 2) bpm = 2;
        G = nsm * bpm;
        if (G < 1) G = 1;
        if (G > 512) G = 512;
    }

    reset_bar<<<1,1>>>();
    mega<<<G, THREADS>>>(
        (const float*)d_in[0],  (const float*)d_in[1],  (const float*)d_in[2],
        (const float*)d_in[3],  (const float*)d_in[4],  (const float*)d_in[5],
        (const float*)d_in[6],  (const float*)d_in[7],  (const float*)d_in[8],
        (const float*)d_in[9],  (const float*)d_in[10], (const float*)d_in[11],
        (const float*)d_in[12], (const float*)d_in[13], (const float*)d_in[14],
        (const float*)d_in[15], (const float*)d_in[16], (const float*)d_in[17],
        (const float*)d_in[18], (const float*)d_in[19], (const float*)d_in[20],
        (const float*)d_in[21], (const float*)d_in[22], (const float*)d_in[23],
        (const float*)d_in[24], (const float*)d_in[25], (const float*)d_in[26],
        (float*)d_out);
}